// round 16
// baseline (speedup 1.0000x reference)
#include <cuda_runtime.h>
#include <cuda_fp16.h>
#include <cstdint>

// ---------------------------------------------------------------------------
// Problem constants
// ---------------------------------------------------------------------------
#define M_TOT 512
#define N_TOT 11008
#define K_TOT 4096
#define KGROUPS (K_TOT / 32)              // 128 groups along K per output feature
#define NGROUPS (N_TOT * KGROUPS)         // 1,409,024 total groups

// GEMM tiling: CTA 128x64x64; 4 warps in 2x2 grid of 64x32 warp tiles
#define BM 128
#define BN 64
#define BK 64                              // 64 fp16 = 128B rows (SW128 atom)
#define NTILES (K_TOT / BK)                // 64
#define NTHREADS 128
#define STAGE_BYTES 18432                  // A 16KB + B records 2KB
#define REC_OFF 16384
#define SMEM_BYTES (2 * STAGE_BYTES)       // 36 KB (double buffer)

#define NREPACK_BLOCKS (NGROUPS / 256)     // 5504
#define NCVT_BLOCKS ((M_TOT * K_TOT / 4) / 256)  // 2048

// Scratch (device globals: no allocation allowed)
__device__ __half g_xh[M_TOT * K_TOT];     // 4 MB   x in fp16
__device__ uint4  g_wpack[NGROUPS];        // 22.5 MB, k-block-major: [kb][n]
                                           // .w = packed halves (2*norm/7, -norm)

// ---------------------------------------------------------------------------
// helpers
// ---------------------------------------------------------------------------
__device__ __forceinline__ uint32_t smem_to_u32(const void* p) {
    uint32_t a;
    asm("{ .reg .u64 t; cvta.to.shared.u64 t, %1; cvt.u32.u64 %0, t; }" : "=r"(a) : "l"(p));
    return a;
}
__device__ __forceinline__ uint32_t sw128(uint32_t off) {
    return off ^ ((off >> 3) & 0x70);
}
#define CP_ASYNC16(dst, src) \
    asm volatile("cp.async.cg.shared.global [%0], [%1], 16;" :: "r"(dst), "l"(src) : "memory")
#define CP_COMMIT() asm volatile("cp.async.commit_group;" ::: "memory")
#define CP_WAIT0()  asm volatile("cp.async.wait_group 0;" ::: "memory")

#define LDMATRIX_X4(r0, r1, r2, r3, addr) \
    asm volatile("ldmatrix.sync.aligned.m8n8.x4.shared.b16 {%0,%1,%2,%3}, [%4];" \
                 : "=r"(r0), "=r"(r1), "=r"(r2), "=r"(r3) : "r"(addr))

#define LDS128(v, addr) \
    asm volatile("ld.shared.v4.u32 {%0,%1,%2,%3}, [%4];" \
                 : "=r"((v).x), "=r"((v).y), "=r"((v).z), "=r"((v).w) : "r"(addr))

// dequant one extracted 6-bit pair -> half2 s*(2q-7) in fragment register form
__device__ __forceinline__ uint32_t deq_pair(uint32_t t, uint32_t h2s, uint32_t hm7) {
    // rr = half2(1024+q_lo, 1024+q_hi) exactly via fp16 mantissa trick
    uint32_t rr = ((t & 7u) | ((t << 13) & 0x70000u)) | 0x64006400u;
    const uint32_t c1024 = 0x64006400u;
    __half2 q = __hsub2(*reinterpret_cast<__half2*>(&rr),
                        *reinterpret_cast<const __half2*>(&c1024));      // exact
    __half2 w = __hfma2(q, *reinterpret_cast<__half2*>(&h2s),
                        *reinterpret_cast<__half2*>(&hm7));              // q*(2n/7) - n
    return *reinterpret_cast<uint32_t*>(&w);
}

// dequant one 16B group record (32 3-bit values) into the 4 b-frag registers
// this thread needs for its two mma k-steps (h=0,1) of this k-group.
// q6 = 6*(lane&3). Pair (v,v+1), v = 16h + 8j + 2*(lane&3), at bit 3v.
__device__ __forceinline__ void deq_rec(uint4 r, uint32_t q6,
                                        uint32_t* bh0, uint32_t* bh1) {
    uint32_t x2 = __funnelshift_r(r.x, r.y, q6);   // realigned bits [0..31]
    uint32_t y2 = __funnelshift_r(r.y, r.z, q6);   // [32..63]
    uint32_t z2 = r.z >> q6;                       // [64..95-q6]
    uint32_t h2s = __byte_perm(r.w, r.w, 0x1010);  // splat lo half: 2n/7
    uint32_t hm7 = __byte_perm(r.w, r.w, 0x3232);  // splat hi half: -n
    bh0[0] = deq_pair(x2,        h2s, hm7);        // h=0 j=0 (bit 0)
    bh0[1] = deq_pair(x2 >> 24,  h2s, hm7);        // h=0 j=1 (bit 24)
    bh1[0] = deq_pair(y2 >> 16,  h2s, hm7);        // h=1 j=0 (bit 48)
    bh1[1] = deq_pair(z2 >> 8,   h2s, hm7);        // h=1 j=1 (bit 72)
}

// ---------------------------------------------------------------------------
// P1 (single launch): repack weights (+inline norm-dtype sniff) AND x->fp16.
// Repack reads are staged through smem for full coalescing.
// ---------------------------------------------------------------------------
__global__ void k_prep(const float* __restrict__ x,
                       const int* __restrict__ q3,
                       const void* __restrict__ norm) {
    const int blk = blockIdx.x;
    if (blk < NREPACK_BLOCKS) {
        __shared__ int4 st[768];
        const int4* q4 = reinterpret_cast<const int4*>(q3);
        const size_t base = (size_t)blk * 768;
        st[threadIdx.x]       = q4[base + threadIdx.x];
        st[threadIdx.x + 256] = q4[base + threadIdx.x + 256];
        st[threadIdx.x + 512] = q4[base + threadIdx.x + 512];

        // ---- inline dtype sniff (norms in (0.01,0.11) by construction).
        // bf16 tested before f32: f32-read of bf16 aliases into range, converse ~never.
        const uint16_t* p16 = (const uint16_t*)norm;
        const float*    p32 = (const float*)norm;
        bool bf_ok = true, f32_ok = true;
#pragma unroll
        for (int i = 0; i < 16; ++i) {
            float fb = __uint_as_float(((uint32_t)p16[i]) << 16);
            if (!(fb > 0.005f && fb < 0.2f)) bf_ok = false;
        }
#pragma unroll
        for (int i = 0; i < 8; ++i) {
            float ff = p32[i];
            if (!(ff > 0.005f && ff < 0.2f)) f32_ok = false;
        }
        const int mode = bf_ok ? 2 : (f32_ok ? 0 : 1);   // 2=bf16,0=f32,1=f16
        __syncthreads();

        const int j = threadIdx.x;
        int4 c0 = st[3 * j], c1 = st[3 * j + 1], c2 = st[3 * j + 2];
        uint4 o;
        o.x = (uint32_t)(c0.x & 255) | ((uint32_t)(c0.y & 255) << 8) |
              ((uint32_t)(c0.z & 255) << 16) | ((uint32_t)(c0.w & 255) << 24);
        o.y = (uint32_t)(c1.x & 255) | ((uint32_t)(c1.y & 255) << 8) |
              ((uint32_t)(c1.z & 255) << 16) | ((uint32_t)(c1.w & 255) << 24);
        o.z = (uint32_t)(c2.x & 255) | ((uint32_t)(c2.y & 255) << 8) |
              ((uint32_t)(c2.z & 255) << 16) | ((uint32_t)(c2.w & 255) << 24);
        const int g = blk * 256 + j;                     // input group: n-major
        float nf;
        if (mode == 0)      nf = p32[g];
        else if (mode == 1) nf = __half2float(((const __half*)norm)[g]);
        else                nf = __uint_as_float(((uint32_t)p16[g]) << 16);
        // pack scale pair: lo = 2n/7 (multiplier), hi = -n (addend)
        __half hlo = __float2half_rn(2.0f * nf / 7.0f);
        __half hhi = __float2half_rn(-nf);
        o.w = (uint32_t)__half_as_ushort(hlo) | ((uint32_t)__half_as_ushort(hhi) << 16);
        const int n  = g / KGROUPS;
        const int kb = g % KGROUPS;
        g_wpack[(size_t)kb * N_TOT + n] = o;             // k-block-major
    } else {
        int i = (blk - NREPACK_BLOCKS) * 256 + threadIdx.x;   // one float4
        float4 v = reinterpret_cast<const float4*>(x)[i];
        __half2* dst = reinterpret_cast<__half2*>(g_xh) + 2 * i;
        dst[0] = __floats2half2_rn(v.x, v.y);
        dst[1] = __floats2half2_rn(v.z, v.w);
    }
}

// ---------------------------------------------------------------------------
// Fused dequant + GEMM: B dequantized straight into mma fragment registers
// (no B smem round trip). A via cp.async + ldmatrix; records via cp.async+LDS.
// ---------------------------------------------------------------------------
__global__ void __launch_bounds__(NTHREADS, 3)
k_gemm(const float* __restrict__ bias, float* __restrict__ out) {
    extern __shared__ char smem[];
    const uint32_t sb = smem_to_u32(smem);

    const int tid  = threadIdx.x;
    const int lane = tid & 31;
    const int warp = tid >> 5;
    const int wm   = warp >> 1;           // 0..1 (64 rows)
    const int wn   = warp & 1;            // 0..1 (32 cols)
    const int n_base = blockIdx.x * BN;
    const int m_base = blockIdx.y * BM;

    const uint32_t a_lane = (uint32_t)(wm * 8192 + (lane & 15) * 128 + (lane >> 4) * 16);
    const uint32_t q6 = 6u * (lane & 3);
    // record LDS base for this thread: n_local = wn*32 + ni*8 + (lane>>2), gk in {0,1}
    const uint32_t rec_lane = (uint32_t)((wn * 32 + (lane >> 2)) * 32);

    float acc[4][4][4];
#pragma unroll
    for (int mi = 0; mi < 4; ++mi)
#pragma unroll
        for (int ni = 0; ni < 4; ++ni)
#pragma unroll
            for (int c = 0; c < 4; ++c) acc[mi][ni][c] = 0.0f;

    auto cpasync = [&](int t, int buf) {
        const uint32_t dbase = sb + buf * STAGE_BYTES;
        const __half* src0 = g_xh + (size_t)m_base * K_TOT + t * BK;
#pragma unroll
        for (int i = 0; i < 8; ++i) {
            int id = i * NTHREADS + tid;          // 0..1023
            int row = id >> 3, c8 = id & 7;
            CP_ASYNC16(dbase + sw128((uint32_t)(row * 128 + c8 * 16)),
                       src0 + (size_t)row * K_TOT + c8 * 8);
        }
        // one 16B weight record per thread: n_local = tid>>1, gk = tid&1
        const uint4* rsrc = g_wpack + (size_t)(2 * t + (tid & 1)) * N_TOT
                                    + n_base + (tid >> 1);
        CP_ASYNC16(dbase + REC_OFF + (uint32_t)tid * 16, rsrc);
        CP_COMMIT();
    };

    // prologue
    cpasync(0, 0);

#pragma unroll 1
    for (int t = 0; t < NTILES; ++t) {
        const int buf = t & 1;
        CP_WAIT0();                // A(t) + rec(t) landed (this thread's view)
        __syncthreads();           // visible to all; prev compute done
        if (t + 1 < NTILES) cpasync(t + 1, buf ^ 1);

        // ---- build all B fragment registers for this tile from records
        uint32_t bfr[4][4][2];     // [ni][ks][j]
        {
            const uint32_t recb = sb + buf * STAGE_BYTES + REC_OFF + rec_lane;
#pragma unroll
            for (int ni = 0; ni < 4; ++ni) {
                uint4 r0, r1;
                LDS128(r0, recb + ni * 256);        // gk=0 -> ks 0,1
                LDS128(r1, recb + ni * 256 + 16);   // gk=1 -> ks 2,3
                deq_rec(r0, q6, bfr[ni][0], bfr[ni][1]);
                deq_rec(r1, q6, bfr[ni][2], bfr[ni][3]);
            }
        }

        // ---- A fragments + mma
        const uint32_t Ab = sb + buf * STAGE_BYTES;
#pragma unroll
        for (int ks = 0; ks < 4; ++ks) {
            uint32_t a[4][4];
#pragma unroll
            for (int mi = 0; mi < 4; ++mi)
                LDMATRIX_X4(a[mi][0], a[mi][1], a[mi][2], a[mi][3],
                            Ab + sw128(a_lane + mi * 2048 + ks * 32));
#pragma unroll
            for (int mi = 0; mi < 4; ++mi)
#pragma unroll
                for (int ni = 0; ni < 4; ++ni)
                    asm volatile(
                        "mma.sync.aligned.m16n8k16.row.col.f32.f16.f16.f32 "
                        "{%0,%1,%2,%3}, {%4,%5,%6,%7}, {%8,%9}, {%0,%1,%2,%3};\n"
                        : "+f"(acc[mi][ni][0]), "+f"(acc[mi][ni][1]),
                          "+f"(acc[mi][ni][2]), "+f"(acc[mi][ni][3])
                        : "r"(a[mi][0]), "r"(a[mi][1]), "r"(a[mi][2]), "r"(a[mi][3]),
                          "r"(bfr[ni][ks][0]), "r"(bfr[ni][ks][1]));
        }
    }

    // epilogue: add bias, write fp32
#pragma unroll
    for (int mi = 0; mi < 4; ++mi) {
        const int r0 = m_base + wm * 64 + mi * 16 + (lane >> 2);
#pragma unroll
        for (int ni = 0; ni < 4; ++ni) {
            const int col = n_base + wn * 32 + ni * 8 + (lane & 3) * 2;
            float2 bb = *reinterpret_cast<const float2*>(bias + col);
            float2 v0 = make_float2(acc[mi][ni][0] + bb.x, acc[mi][ni][1] + bb.y);
            float2 v1 = make_float2(acc[mi][ni][2] + bb.x, acc[mi][ni][3] + bb.y);
            *reinterpret_cast<float2*>(out + (size_t)r0 * N_TOT + col) = v0;
            *reinterpret_cast<float2*>(out + (size_t)(r0 + 8) * N_TOT + col) = v1;
        }
    }
}

// ---------------------------------------------------------------------------
// Launch
// ---------------------------------------------------------------------------
extern "C" void kernel_launch(void* const* d_in, const int* in_sizes, int n_in,
                              void* d_out, int out_size) {
    const float* x    = (const float*)d_in[0];
    const int*   q3   = (const int*)d_in[1];
    const void*  norm = (const void*)d_in[2];
    const float* bias = (const float*)d_in[3];
    float*       out  = (float*)d_out;

    // single fused pre-pass launch (repack + sniff + x->fp16)
    k_prep<<<NREPACK_BLOCKS + NCVT_BLOCKS, 256>>>(x, q3, norm);

    cudaFuncSetAttribute((const void*)k_gemm,
                         cudaFuncAttributeMaxDynamicSharedMemorySize, SMEM_BYTES);
    dim3 grid(N_TOT / BN, M_TOT / BM);   // 172 x 4 = 688 CTAs
    k_gemm<<<grid, NTHREADS, SMEM_BYTES>>>(bias, out);
}